// round 1
// baseline (speedup 1.0000x reference)
#include <cuda_runtime.h>
#include <cstddef>

// ---------------------------------------------------------------------------
// Problem constants
// ---------------------------------------------------------------------------
constexpr int B_  = 2;
constexpr int S_  = 2048;
constexpr int D_  = 1024;   // d_model
constexpr int H_  = 16;     // heads
constexpr int DH_ = 64;     // head dim
constexpr int M_  = B_ * S_;  // 4096 rows for projections

// ---------------------------------------------------------------------------
// Scratch (device globals: no allocations allowed)
// ---------------------------------------------------------------------------
__device__ float g_q[(size_t)B_ * H_ * S_ * DH_];     // [B,H,S,DH]
__device__ float g_k[(size_t)B_ * H_ * S_ * DH_];
__device__ float g_v[(size_t)B_ * H_ * S_ * DH_];
__device__ float g_attn[(size_t)M_ * D_];             // [B*S, D] attention output

// ---------------------------------------------------------------------------
// GEMM: out[m][n] = sum_k A[m][k] * W[n][k]   (i.e. x @ W^T, both row-major)
// M=4096, N=1024, K=1024. Tile 128x128xBK16, 256 threads, 8x8 per thread.
// If SCATTER: write into head-separated layout [B,H,S,DH] (for Q/K/V).
// Else: plain row-major [M,N].
// ---------------------------------------------------------------------------
template <bool SCATTER>
__global__ __launch_bounds__(256, 2)
void gemm128(const float* __restrict__ A, const float* __restrict__ W,
             float* __restrict__ out)
{
    constexpr int BM = 128, BN = 128, BK = 16;
    __shared__ float As[BK][BM + 4];   // stride 132 floats (528B, 16B aligned)
    __shared__ float Bs[BK][BN + 4];

    const int tid = threadIdx.x;          // 0..255
    const int tx  = tid & 15;             // 0..15
    const int ty  = tid >> 4;             // 0..15
    const int bm  = blockIdx.y * BM;
    const int bn  = blockIdx.x * BN;

    const int lrow = tid >> 2;            // 0..63
    const int lk   = (tid & 3) << 2;      // 0,4,8,12

    float acc[8][8];
#pragma unroll
    for (int i = 0; i < 8; i++)
#pragma unroll
        for (int j = 0; j < 8; j++) acc[i][j] = 0.0f;

    for (int k0 = 0; k0 < D_; k0 += BK) {
        float4 a0 = *(const float4*)(A + (size_t)(bm + lrow)      * D_ + k0 + lk);
        float4 a1 = *(const float4*)(A + (size_t)(bm + lrow + 64) * D_ + k0 + lk);
        float4 b0 = *(const float4*)(W + (size_t)(bn + lrow)      * D_ + k0 + lk);
        float4 b1 = *(const float4*)(W + (size_t)(bn + lrow + 64) * D_ + k0 + lk);

        __syncthreads();   // previous iteration's compute done before overwrite

        As[lk + 0][lrow] = a0.x; As[lk + 1][lrow] = a0.y;
        As[lk + 2][lrow] = a0.z; As[lk + 3][lrow] = a0.w;
        As[lk + 0][lrow + 64] = a1.x; As[lk + 1][lrow + 64] = a1.y;
        As[lk + 2][lrow + 64] = a1.z; As[lk + 3][lrow + 64] = a1.w;
        Bs[lk + 0][lrow] = b0.x; Bs[lk + 1][lrow] = b0.y;
        Bs[lk + 2][lrow] = b0.z; Bs[lk + 3][lrow] = b0.w;
        Bs[lk + 0][lrow + 64] = b1.x; Bs[lk + 1][lrow + 64] = b1.y;
        Bs[lk + 2][lrow + 64] = b1.z; Bs[lk + 3][lrow + 64] = b1.w;

        __syncthreads();

#pragma unroll
        for (int kk = 0; kk < BK; kk++) {
            float a[8], b[8];
            *(float4*)(a)     = *(const float4*)&As[kk][ty * 8];
            *(float4*)(a + 4) = *(const float4*)&As[kk][ty * 8 + 4];
            *(float4*)(b)     = *(const float4*)&Bs[kk][tx * 8];
            *(float4*)(b + 4) = *(const float4*)&Bs[kk][tx * 8 + 4];
#pragma unroll
            for (int i = 0; i < 8; i++)
#pragma unroll
                for (int j = 0; j < 8; j++)
                    acc[i][j] += a[i] * b[j];
        }
    }

    // Epilogue
#pragma unroll
    for (int i = 0; i < 8; i++) {
        const int m = bm + ty * 8 + i;
#pragma unroll
        for (int j = 0; j < 8; j++) {
            const int n = bn + tx * 8 + j;
            if (SCATTER) {
                const int b_ = m >> 11;            // m / 2048
                const int s_ = m & 2047;
                const int h_ = n >> 6;             // n / 64
                const int d_ = n & 63;
                out[(((size_t)(b_ * H_ + h_) * S_ + s_) << 6) + d_] = acc[i][j];
            } else {
                out[(size_t)m * D_ + n] = acc[i][j];
            }
        }
    }
}

// ---------------------------------------------------------------------------
// Flash attention (fp32, causal). One block per (b, h, 64-row q tile).
// 256 threads = 16x16; each thread owns a 4x4 sub-tile of the 64x64 score
// block and a 4x4 sub-tile of the 64x64 output (rows x head_dim).
// smem: Q^T [d][r], K^T [d][c] (aliased with P [r][c] after use), V [c][d].
// Exactly 3 * 64*64*4 = 48KB -> static smem, no attribute calls needed.
// ---------------------------------------------------------------------------
__global__ __launch_bounds__(256, 2)
void attn_kernel(const float* __restrict__ Q, const float* __restrict__ K,
                 const float* __restrict__ V, float* __restrict__ Out)
{
    __shared__ float Qst[64][64];   // Q^T: [d][row]
    __shared__ float KPs[64][64];   // K^T: [d][col]  -> later P: [row][col]
    __shared__ float Vs[64][64];    // V:   [col(seq)][d]

    const int tid = threadIdx.x;
    const int tx  = tid & 15;
    const int ty  = tid >> 4;
    const int q0  = blockIdx.x * 64;
    const int h   = blockIdx.y;
    const int b   = blockIdx.z;

    const size_t base = (size_t)(b * H_ + h) * S_ * DH_;
    const float* Qp = Q + base + (size_t)q0 * DH_;

    // Load Q tile, transposed into Qst[d][r]
    for (int idx = tid; idx < 64 * 16; idx += 256) {
        const int r  = idx >> 4;
        const int dq = (idx & 15) << 2;
        float4 v = *(const float4*)(Qp + r * DH_ + dq);
        Qst[dq + 0][r] = v.x; Qst[dq + 1][r] = v.y;
        Qst[dq + 2][r] = v.z; Qst[dq + 3][r] = v.w;
    }

    float o[4][4];
    float mrow[4], lrow[4];
#pragma unroll
    for (int i = 0; i < 4; i++) {
        mrow[i] = -1e30f;
        lrow[i] = 0.0f;
#pragma unroll
        for (int j = 0; j < 4; j++) o[i][j] = 0.0f;
    }

    constexpr float scale = 0.125f;  // 1/sqrt(64)

    for (int k0 = 0; k0 <= q0; k0 += 64) {
        __syncthreads();  // prior iter's P/V reads done (and Qst loaded, iter 0)

        // Load K tile transposed -> KPs[d][c]; V tile straight -> Vs[c][d]
        for (int idx = tid; idx < 64 * 16; idx += 256) {
            const int c  = idx >> 4;
            const int dq = (idx & 15) << 2;
            float4 kv = *(const float4*)(K + base + (size_t)(k0 + c) * DH_ + dq);
            KPs[dq + 0][c] = kv.x; KPs[dq + 1][c] = kv.y;
            KPs[dq + 2][c] = kv.z; KPs[dq + 3][c] = kv.w;
            float4 vv = *(const float4*)(V + base + (size_t)(k0 + c) * DH_ + dq);
            *(float4*)&Vs[c][dq] = vv;
        }
        __syncthreads();

        // Scores: sc = Q @ K^T   (contract over d)
        float sc[4][4];
#pragma unroll
        for (int i = 0; i < 4; i++)
#pragma unroll
            for (int j = 0; j < 4; j++) sc[i][j] = 0.0f;

#pragma unroll 16
        for (int kk = 0; kk < 64; kk++) {
            float a[4], bb[4];
            *(float4*)a  = *(const float4*)&Qst[kk][ty * 4];
            *(float4*)bb = *(const float4*)&KPs[kk][tx * 4];
#pragma unroll
            for (int i = 0; i < 4; i++)
#pragma unroll
                for (int j = 0; j < 4; j++)
                    sc[i][j] += a[i] * bb[j];
        }

        // Scale + causal mask (mask only needed on the diagonal tile)
        if (k0 == q0) {
#pragma unroll
            for (int i = 0; i < 4; i++) {
                const int r = ty * 4 + i;
#pragma unroll
                for (int j = 0; j < 4; j++) {
                    const int c = tx * 4 + j;
                    sc[i][j] = (c > r) ? -1e30f : sc[i][j] * scale;
                }
            }
        } else {
#pragma unroll
            for (int i = 0; i < 4; i++)
#pragma unroll
                for (int j = 0; j < 4; j++) sc[i][j] *= scale;
        }

        // Online softmax (row groups of 16 threads along tx, width-16 shuffles)
#pragma unroll
        for (int i = 0; i < 4; i++) {
            float mloc = fmaxf(fmaxf(sc[i][0], sc[i][1]), fmaxf(sc[i][2], sc[i][3]));
#pragma unroll
            for (int off = 8; off; off >>= 1)
                mloc = fmaxf(mloc, __shfl_xor_sync(0xffffffffu, mloc, off, 16));
            const float mnew = fmaxf(mrow[i], mloc);
            const float corr = __expf(mrow[i] - mnew);
            mrow[i] = mnew;
            float rs = 0.0f;
#pragma unroll
            for (int j = 0; j < 4; j++) {
                const float p = __expf(sc[i][j] - mnew);
                sc[i][j] = p;
                rs += p;
            }
#pragma unroll
            for (int off = 8; off; off >>= 1)
                rs += __shfl_xor_sync(0xffffffffu, rs, off, 16);
            lrow[i] = lrow[i] * corr + rs;
#pragma unroll
            for (int j = 0; j < 4; j++) o[i][j] *= corr;
        }

        __syncthreads();  // all K^T reads complete before P overwrites KPs

        // Store P into KPs as [row][col]
#pragma unroll
        for (int i = 0; i < 4; i++)
            *(float4*)&KPs[ty * 4 + i][tx * 4] =
                make_float4(sc[i][0], sc[i][1], sc[i][2], sc[i][3]);
        __syncthreads();

        // O += P @ V  (contract over seq col c)
#pragma unroll 16
        for (int c = 0; c < 64; c++) {
            float bb[4];
            *(float4*)bb = *(const float4*)&Vs[c][tx * 4];
#pragma unroll
            for (int i = 0; i < 4; i++) {
                const float p = KPs[ty * 4 + i][c];
#pragma unroll
                for (int j = 0; j < 4; j++)
                    o[i][j] += p * bb[j];
            }
        }
    }

    // Normalize and write to [B, S, D] (heads re-interleaved)
#pragma unroll
    for (int i = 0; i < 4; i++) {
        const float inv = 1.0f / lrow[i];
        const int r = q0 + ty * 4 + i;
        float4 res = make_float4(o[i][0] * inv, o[i][1] * inv,
                                 o[i][2] * inv, o[i][3] * inv);
        *(float4*)&Out[((size_t)(b * S_) + r) * D_ + h * DH_ + tx * 4] = res;
    }
}

// ---------------------------------------------------------------------------
// Launch
// ---------------------------------------------------------------------------
extern "C" void kernel_launch(void* const* d_in, const int* in_sizes, int n_in,
                              void* d_out, int out_size)
{
    const float* x  = (const float*)d_in[0];
    const float* wq = (const float*)d_in[1];
    const float* wk = (const float*)d_in[2];
    const float* wv = (const float*)d_in[3];
    const float* wo = (const float*)d_in[4];
    float* out = (float*)d_out;

    void *pq, *pk, *pv, *pa;
    cudaGetSymbolAddress(&pq, g_q);
    cudaGetSymbolAddress(&pk, g_k);
    cudaGetSymbolAddress(&pv, g_v);
    cudaGetSymbolAddress(&pa, g_attn);
    float* q  = (float*)pq;
    float* k  = (float*)pk;
    float* v  = (float*)pv;
    float* ao = (float*)pa;

    dim3 gemm_grid(D_ / 128, M_ / 128);   // (8, 32)
    gemm128<true><<<gemm_grid, 256>>>(x, wq, q);
    gemm128<true><<<gemm_grid, 256>>>(x, wk, k);
    gemm128<true><<<gemm_grid, 256>>>(x, wv, v);

    dim3 attn_grid(S_ / 64, H_, B_);      // (32, 16, 2)
    attn_kernel<<<attn_grid, 256>>>(q, k, v, ao);

    gemm128<false><<<gemm_grid, 256>>>(ao, wo, out);
}

// round 3
// speedup vs baseline: 1.4178x; 1.4178x over previous
#include <cuda_runtime.h>
#include <cuda_bf16.h>
#include <cstdint>
#include <cstddef>

// ---------------------------------------------------------------------------
// Problem constants
// ---------------------------------------------------------------------------
constexpr int B_  = 2;
constexpr int S_  = 2048;
constexpr int D_  = 1024;
constexpr int H_  = 16;
constexpr int DH_ = 64;
constexpr int M_  = B_ * S_;   // 4096

// ---------------------------------------------------------------------------
// Scratch
// ---------------------------------------------------------------------------
__device__ float g_q[(size_t)B_ * H_ * S_ * DH_];
__device__ float g_k[(size_t)B_ * H_ * S_ * DH_];
__device__ float g_v[(size_t)B_ * H_ * S_ * DH_];
__device__ float g_attn[(size_t)M_ * D_];

// ---------------------------------------------------------------------------
// mma.sync m16n8k16 bf16 (sm_80+ path; no arch-'a' feature needed)
// ---------------------------------------------------------------------------
__device__ __forceinline__ void mma16816(float* c, const uint32_t* a, const uint32_t* b) {
    asm volatile(
        "mma.sync.aligned.m16n8k16.row.col.f32.bf16.bf16.f32 "
        "{%0,%1,%2,%3}, {%4,%5,%6,%7}, {%8,%9}, {%0,%1,%2,%3};"
        : "+f"(c[0]), "+f"(c[1]), "+f"(c[2]), "+f"(c[3])
        : "r"(a[0]), "r"(a[1]), "r"(a[2]), "r"(a[3]), "r"(b[0]), "r"(b[1]));
}

// ---------------------------------------------------------------------------
// Tensor-core GEMM via mma.sync: out[m][n] = sum_k A[m][k] * W[n][k]
// fp32 accuracy via bf16 split: A ~ Ah + Al; AB ~ AhBh + AhBl + AlBh.
// Block: 256 thr (8 warps), tile 128(M) x 128(N) x 32(K).
// Warp tile: 64x32 -> 4x4 m16n8k16 tiles, fp32 acc.
// Smem rows padded to 72B (36 bf16) -> conflict-free b32 fragment loads.
// ---------------------------------------------------------------------------
constexpr int RS = 36;  // smem row stride in bf16 elements (72 B)

template <bool SCATTER>
__global__ __launch_bounds__(256)
void gemm_mma(const float* __restrict__ A, const float* __restrict__ W,
              float* __restrict__ out)
{
    __shared__ __nv_bfloat16 Ah[128 * RS];
    __shared__ __nv_bfloat16 Al[128 * RS];
    __shared__ __nv_bfloat16 Bh[128 * RS];
    __shared__ __nv_bfloat16 Bl[128 * RS];

    const int tid  = threadIdx.x;
    const int wid  = tid >> 5;
    const int lane = tid & 31;
    const int wm   = wid >> 2;          // 0..1 : 64-row group
    const int wn   = wid & 3;           // 0..3 : 32-col group
    const int bn   = blockIdx.x * 128;
    const int bm   = blockIdx.y * 128;

    const int lq = lane >> 2;           // 0..7
    const int lr = (lane & 3) << 1;     // 0,2,4,6

    float acc[4][4][4];
#pragma unroll
    for (int i = 0; i < 4; i++)
#pragma unroll
        for (int j = 0; j < 4; j++)
#pragma unroll
            for (int r = 0; r < 4; r++) acc[i][j][r] = 0.0f;

    // Per-thread staging assignment: 4 float4 for A, 4 for B.
    // f = tid + i*256 -> row = f>>3 (0..127), c4 = f&7 (k = c4*4).
    const int srow = tid >> 3;
    const int sc4  = tid & 7;

    float4 pfA[4], pfB[4];

    auto load_tile = [&](int k0) {
#pragma unroll
        for (int i = 0; i < 4; i++) {
            const int r = srow + i * 32;
            pfA[i] = *(const float4*)(A + (size_t)(bm + r) * D_ + k0 + sc4 * 4);
            pfB[i] = *(const float4*)(W + (size_t)(bn + r) * D_ + k0 + sc4 * 4);
        }
    };

    auto split_store = [&](__nv_bfloat16* hiBase, __nv_bfloat16* loBase,
                           int r, float4 f) {
        __nv_bfloat162 h01 = __floats2bfloat162_rn(f.x, f.y);
        __nv_bfloat162 h23 = __floats2bfloat162_rn(f.z, f.w);
        float lx = f.x - __bfloat162float(h01.x);
        float ly = f.y - __bfloat162float(h01.y);
        float lz = f.z - __bfloat162float(h23.x);
        float lw = f.w - __bfloat162float(h23.y);
        __nv_bfloat162 l01 = __floats2bfloat162_rn(lx, ly);
        __nv_bfloat162 l23 = __floats2bfloat162_rn(lz, lw);
        __nv_bfloat16* hp = hiBase + r * RS + sc4 * 4;
        __nv_bfloat16* lp = loBase + r * RS + sc4 * 4;
        *(__nv_bfloat162*)hp       = h01;
        *(__nv_bfloat162*)(hp + 2) = h23;
        *(__nv_bfloat162*)lp       = l01;
        *(__nv_bfloat162*)(lp + 2) = l23;
    };

    load_tile(0);

    for (int kt = 0; kt < 32; ++kt) {
        __syncthreads();   // previous compute done before smem overwrite
#pragma unroll
        for (int i = 0; i < 4; i++) {
            split_store(Ah, Al, srow + i * 32, pfA[i]);
            split_store(Bh, Bl, srow + i * 32, pfB[i]);
        }
        __syncthreads();

        if (kt < 31) load_tile((kt + 1) * 32);   // overlap gmem with mma

#pragma unroll
        for (int ks = 0; ks < 2; ++ks) {
            const int kb = ks * 16 + lr;         // this lane's k base (pairs)

            // B fragments for all 4 n-tiles (held in regs)
            uint32_t bh[4][2], bl[4][2];
#pragma unroll
            for (int nt = 0; nt < 4; ++nt) {
                const int n = wn * 32 + nt * 8 + lq;
                bh[nt][0] = *(const uint32_t*)&Bh[n * RS + kb];
                bh[nt][1] = *(const uint32_t*)&Bh[n * RS + kb + 8];
                bl[nt][0] = *(const uint32_t*)&Bl[n * RS + kb];
                bl[nt][1] = *(const uint32_t*)&Bl[n * RS + kb + 8];
            }

#pragma unroll
            for (int mt = 0; mt < 4; ++mt) {
                const int r = wm * 64 + mt * 16 + lq;
                uint32_t ah[4], al[4];
                ah[0] = *(const uint32_t*)&Ah[r * RS + kb];
                ah[1] = *(const uint32_t*)&Ah[(r + 8) * RS + kb];
                ah[2] = *(const uint32_t*)&Ah[r * RS + kb + 8];
                ah[3] = *(const uint32_t*)&Ah[(r + 8) * RS + kb + 8];
                al[0] = *(const uint32_t*)&Al[r * RS + kb];
                al[1] = *(const uint32_t*)&Al[(r + 8) * RS + kb];
                al[2] = *(const uint32_t*)&Al[r * RS + kb + 8];
                al[3] = *(const uint32_t*)&Al[(r + 8) * RS + kb + 8];
#pragma unroll
                for (int nt = 0; nt < 4; ++nt) {
                    mma16816(acc[mt][nt], ah, bh[nt]);
                    mma16816(acc[mt][nt], ah, bl[nt]);
                    mma16816(acc[mt][nt], al, bh[nt]);
                }
            }
        }
    }

    // Epilogue. Acc layout: c0,c1 -> (row lq, col lr..lr+1); c2,c3 -> row lq+8.
#pragma unroll
    for (int mt = 0; mt < 4; ++mt) {
#pragma unroll
        for (int nt = 0; nt < 4; ++nt) {
            const int n  = bn + wn * 32 + nt * 8 + lr;
            const int m0 = bm + wm * 64 + mt * 16 + lq;
#pragma unroll
            for (int half = 0; half < 2; ++half) {
                const int m = m0 + half * 8;
                float2 v = make_float2(acc[mt][nt][half * 2],
                                       acc[mt][nt][half * 2 + 1]);
                if (SCATTER) {
                    const int b_ = m >> 11;
                    const int s_ = m & 2047;
                    const int h_ = n >> 6;
                    const int d_ = n & 63;
                    *(float2*)&out[(((size_t)(b_ * H_ + h_) * S_ + s_) << 6) + d_] = v;
                } else {
                    *(float2*)&out[(size_t)m * D_ + n] = v;
                }
            }
        }
    }
}

// ---------------------------------------------------------------------------
// Flash attention (fp32, causal) — unchanged (passing baseline).
// ---------------------------------------------------------------------------
__global__ __launch_bounds__(256, 2)
void attn_kernel(const float* __restrict__ Q, const float* __restrict__ K,
                 const float* __restrict__ V, float* __restrict__ Out)
{
    __shared__ float Qst[64][64];
    __shared__ float KPs[64][64];
    __shared__ float Vs[64][64];

    const int tid = threadIdx.x;
    const int tx  = tid & 15;
    const int ty  = tid >> 4;
    const int q0  = blockIdx.x * 64;
    const int h   = blockIdx.y;
    const int b   = blockIdx.z;

    const size_t base = (size_t)(b * H_ + h) * S_ * DH_;
    const float* Qp = Q + base + (size_t)q0 * DH_;

    for (int idx = tid; idx < 64 * 16; idx += 256) {
        const int r  = idx >> 4;
        const int dq = (idx & 15) << 2;
        float4 v = *(const float4*)(Qp + r * DH_ + dq);
        Qst[dq + 0][r] = v.x; Qst[dq + 1][r] = v.y;
        Qst[dq + 2][r] = v.z; Qst[dq + 3][r] = v.w;
    }

    float o[4][4];
    float mrow[4], lrow[4];
#pragma unroll
    for (int i = 0; i < 4; i++) {
        mrow[i] = -1e30f;
        lrow[i] = 0.0f;
#pragma unroll
        for (int j = 0; j < 4; j++) o[i][j] = 0.0f;
    }

    constexpr float scale = 0.125f;

    for (int k0 = 0; k0 <= q0; k0 += 64) {
        __syncthreads();

        for (int idx = tid; idx < 64 * 16; idx += 256) {
            const int c  = idx >> 4;
            const int dq = (idx & 15) << 2;
            float4 kv = *(const float4*)(K + base + (size_t)(k0 + c) * DH_ + dq);
            KPs[dq + 0][c] = kv.x; KPs[dq + 1][c] = kv.y;
            KPs[dq + 2][c] = kv.z; KPs[dq + 3][c] = kv.w;
            float4 vv = *(const float4*)(V + base + (size_t)(k0 + c) * DH_ + dq);
            *(float4*)&Vs[c][dq] = vv;
        }
        __syncthreads();

        float sc[4][4];
#pragma unroll
        for (int i = 0; i < 4; i++)
#pragma unroll
            for (int j = 0; j < 4; j++) sc[i][j] = 0.0f;

#pragma unroll 16
        for (int kk = 0; kk < 64; kk++) {
            float a[4], bb[4];
            *(float4*)a  = *(const float4*)&Qst[kk][ty * 4];
            *(float4*)bb = *(const float4*)&KPs[kk][tx * 4];
#pragma unroll
            for (int i = 0; i < 4; i++)
#pragma unroll
                for (int j = 0; j < 4; j++)
                    sc[i][j] += a[i] * bb[j];
        }

        if (k0 == q0) {
#pragma unroll
            for (int i = 0; i < 4; i++) {
                const int r = ty * 4 + i;
#pragma unroll
                for (int j = 0; j < 4; j++) {
                    const int c = tx * 4 + j;
                    sc[i][j] = (c > r) ? -1e30f : sc[i][j] * scale;
                }
            }
        } else {
#pragma unroll
            for (int i = 0; i < 4; i++)
#pragma unroll
                for (int j = 0; j < 4; j++) sc[i][j] *= scale;
        }

#pragma unroll
        for (int i = 0; i < 4; i++) {
            float mloc = fmaxf(fmaxf(sc[i][0], sc[i][1]), fmaxf(sc[i][2], sc[i][3]));
#pragma unroll
            for (int off = 8; off; off >>= 1)
                mloc = fmaxf(mloc, __shfl_xor_sync(0xffffffffu, mloc, off, 16));
            const float mnew = fmaxf(mrow[i], mloc);
            const float corr = __expf(mrow[i] - mnew);
            mrow[i] = mnew;
            float rs = 0.0f;
#pragma unroll
            for (int j = 0; j < 4; j++) {
                const float p = __expf(sc[i][j] - mnew);
                sc[i][j] = p;
                rs += p;
            }
#pragma unroll
            for (int off = 8; off; off >>= 1)
                rs += __shfl_xor_sync(0xffffffffu, rs, off, 16);
            lrow[i] = lrow[i] * corr + rs;
#pragma unroll
            for (int j = 0; j < 4; j++) o[i][j] *= corr;
        }

        __syncthreads();

#pragma unroll
        for (int i = 0; i < 4; i++)
            *(float4*)&KPs[ty * 4 + i][tx * 4] =
                make_float4(sc[i][0], sc[i][1], sc[i][2], sc[i][3]);
        __syncthreads();

#pragma unroll 16
        for (int c = 0; c < 64; c++) {
            float bb[4];
            *(float4*)bb = *(const float4*)&Vs[c][tx * 4];
#pragma unroll
            for (int i = 0; i < 4; i++) {
                const float p = KPs[ty * 4 + i][c];
#pragma unroll
                for (int j = 0; j < 4; j++)
                    o[i][j] += p * bb[j];
            }
        }
    }

#pragma unroll
    for (int i = 0; i < 4; i++) {
        const float inv = 1.0f / lrow[i];
        const int r = q0 + ty * 4 + i;
        float4 res = make_float4(o[i][0] * inv, o[i][1] * inv,
                                 o[i][2] * inv, o[i][3] * inv);
        *(float4*)&Out[((size_t)(b * S_) + r) * D_ + h * DH_ + tx * 4] = res;
    }
}

// ---------------------------------------------------------------------------
// Launch
// ---------------------------------------------------------------------------
extern "C" void kernel_launch(void* const* d_in, const int* in_sizes, int n_in,
                              void* d_out, int out_size)
{
    const float* x  = (const float*)d_in[0];
    const float* wq = (const float*)d_in[1];
    const float* wk = (const float*)d_in[2];
    const float* wv = (const float*)d_in[3];
    const float* wo = (const float*)d_in[4];
    float* out = (float*)d_out;

    void *pq, *pk, *pv, *pa;
    cudaGetSymbolAddress(&pq, g_q);
    cudaGetSymbolAddress(&pk, g_k);
    cudaGetSymbolAddress(&pv, g_v);
    cudaGetSymbolAddress(&pa, g_attn);
    float* q  = (float*)pq;
    float* k  = (float*)pk;
    float* v  = (float*)pv;
    float* ao = (float*)pa;

    dim3 gemm_grid(D_ / 128, M_ / 128);   // (8, 32)
    gemm_mma<true><<<gemm_grid, 256>>>(x, wq, q);
    gemm_mma<true><<<gemm_grid, 256>>>(x, wk, k);
    gemm_mma<true><<<gemm_grid, 256>>>(x, wv, v);

    dim3 attn_grid(S_ / 64, H_, B_);      // (32, 16, 2)
    attn_kernel<<<attn_grid, 256>>>(q, k, v, ao);

    gemm_mma<false><<<gemm_grid, 256>>>(ao, wo, out);
}

// round 4
// speedup vs baseline: 2.2035x; 1.5542x over previous
#include <cuda_runtime.h>
#include <cuda_bf16.h>
#include <cstdint>
#include <cstddef>

// ---------------------------------------------------------------------------
// Problem constants
// ---------------------------------------------------------------------------
constexpr int B_  = 2;
constexpr int S_  = 2048;
constexpr int D_  = 1024;
constexpr int H_  = 16;
constexpr int DH_ = 64;
constexpr int M_  = B_ * S_;   // 4096

// ---------------------------------------------------------------------------
// Scratch
// ---------------------------------------------------------------------------
__device__ float g_q[(size_t)B_ * H_ * S_ * DH_];
__device__ float g_k[(size_t)B_ * H_ * S_ * DH_];
__device__ float g_v[(size_t)B_ * H_ * S_ * DH_];
__device__ float g_attn[(size_t)M_ * D_];

// ---------------------------------------------------------------------------
// mma.sync m16n8k16 bf16 (sm_80+ path)
// ---------------------------------------------------------------------------
__device__ __forceinline__ void mma16816(float* c, const uint32_t* a, const uint32_t* b) {
    asm volatile(
        "mma.sync.aligned.m16n8k16.row.col.f32.bf16.bf16.f32 "
        "{%0,%1,%2,%3}, {%4,%5,%6,%7}, {%8,%9}, {%0,%1,%2,%3};"
        : "+f"(c[0]), "+f"(c[1]), "+f"(c[2]), "+f"(c[3])
        : "r"(a[0]), "r"(a[1]), "r"(a[2]), "r"(a[3]), "r"(b[0]), "r"(b[1]));
}

// Split a pair of floats into bf16 hi + bf16 lo (residual), packed as b32.
__device__ __forceinline__ void split2(float x, float y, uint32_t& hi, uint32_t& lo) {
    __nv_bfloat162 h = __floats2bfloat162_rn(x, y);
    float rx = x - __bfloat162float(h.x);
    float ry = y - __bfloat162float(h.y);
    __nv_bfloat162 l = __floats2bfloat162_rn(rx, ry);
    hi = *reinterpret_cast<uint32_t*>(&h);
    lo = *reinterpret_cast<uint32_t*>(&l);
}

// ---------------------------------------------------------------------------
// Tensor-core GEMM via mma.sync: out[m][n] = sum_k A[m][k] * W[n][k]
// (unchanged from Round 3 — validated at rel_err 1.45e-5)
// ---------------------------------------------------------------------------
constexpr int RS = 36;  // gemm smem row stride in bf16 (72 B)

template <bool SCATTER>
__global__ __launch_bounds__(256)
void gemm_mma(const float* __restrict__ A, const float* __restrict__ W,
              float* __restrict__ out)
{
    __shared__ __nv_bfloat16 Ah[128 * RS];
    __shared__ __nv_bfloat16 Al[128 * RS];
    __shared__ __nv_bfloat16 Bh[128 * RS];
    __shared__ __nv_bfloat16 Bl[128 * RS];

    const int tid  = threadIdx.x;
    const int wid  = tid >> 5;
    const int lane = tid & 31;
    const int wm   = wid >> 2;
    const int wn   = wid & 3;
    const int bn   = blockIdx.x * 128;
    const int bm   = blockIdx.y * 128;

    const int lq = lane >> 2;
    const int lr = (lane & 3) << 1;

    float acc[4][4][4];
#pragma unroll
    for (int i = 0; i < 4; i++)
#pragma unroll
        for (int j = 0; j < 4; j++)
#pragma unroll
            for (int r = 0; r < 4; r++) acc[i][j][r] = 0.0f;

    const int srow = tid >> 3;
    const int sc4  = tid & 7;

    float4 pfA[4], pfB[4];

    auto load_tile = [&](int k0) {
#pragma unroll
        for (int i = 0; i < 4; i++) {
            const int r = srow + i * 32;
            pfA[i] = *(const float4*)(A + (size_t)(bm + r) * D_ + k0 + sc4 * 4);
            pfB[i] = *(const float4*)(W + (size_t)(bn + r) * D_ + k0 + sc4 * 4);
        }
    };

    auto split_store = [&](__nv_bfloat16* hiBase, __nv_bfloat16* loBase,
                           int r, float4 f) {
        uint32_t h01, l01, h23, l23;
        split2(f.x, f.y, h01, l01);
        split2(f.z, f.w, h23, l23);
        __nv_bfloat16* hp = hiBase + r * RS + sc4 * 4;
        __nv_bfloat16* lp = loBase + r * RS + sc4 * 4;
        *(uint32_t*)hp       = h01;
        *(uint32_t*)(hp + 2) = h23;
        *(uint32_t*)lp       = l01;
        *(uint32_t*)(lp + 2) = l23;
    };

    load_tile(0);

    for (int kt = 0; kt < 32; ++kt) {
        __syncthreads();
#pragma unroll
        for (int i = 0; i < 4; i++) {
            split_store(Ah, Al, srow + i * 32, pfA[i]);
            split_store(Bh, Bl, srow + i * 32, pfB[i]);
        }
        __syncthreads();

        if (kt < 31) load_tile((kt + 1) * 32);

#pragma unroll
        for (int ks = 0; ks < 2; ++ks) {
            const int kb = ks * 16 + lr;

            uint32_t bh[4][2], bl[4][2];
#pragma unroll
            for (int nt = 0; nt < 4; ++nt) {
                const int n = wn * 32 + nt * 8 + lq;
                bh[nt][0] = *(const uint32_t*)&Bh[n * RS + kb];
                bh[nt][1] = *(const uint32_t*)&Bh[n * RS + kb + 8];
                bl[nt][0] = *(const uint32_t*)&Bl[n * RS + kb];
                bl[nt][1] = *(const uint32_t*)&Bl[n * RS + kb + 8];
            }

#pragma unroll
            for (int mt = 0; mt < 4; ++mt) {
                const int r = wm * 64 + mt * 16 + lq;
                uint32_t ah[4], al[4];
                ah[0] = *(const uint32_t*)&Ah[r * RS + kb];
                ah[1] = *(const uint32_t*)&Ah[(r + 8) * RS + kb];
                ah[2] = *(const uint32_t*)&Ah[r * RS + kb + 8];
                ah[3] = *(const uint32_t*)&Ah[(r + 8) * RS + kb + 8];
                al[0] = *(const uint32_t*)&Al[r * RS + kb];
                al[1] = *(const uint32_t*)&Al[(r + 8) * RS + kb];
                al[2] = *(const uint32_t*)&Al[r * RS + kb + 8];
                al[3] = *(const uint32_t*)&Al[(r + 8) * RS + kb + 8];
#pragma unroll
                for (int nt = 0; nt < 4; ++nt) {
                    mma16816(acc[mt][nt], ah, bh[nt]);
                    mma16816(acc[mt][nt], ah, bl[nt]);
                    mma16816(acc[mt][nt], al, bh[nt]);
                }
            }
        }
    }

#pragma unroll
    for (int mt = 0; mt < 4; ++mt) {
#pragma unroll
        for (int nt = 0; nt < 4; ++nt) {
            const int n  = bn + wn * 32 + nt * 8 + lr;
            const int m0 = bm + wm * 64 + mt * 16 + lq;
#pragma unroll
            for (int half = 0; half < 2; ++half) {
                const int m = m0 + half * 8;
                float2 v = make_float2(acc[mt][nt][half * 2],
                                       acc[mt][nt][half * 2 + 1]);
                if (SCATTER) {
                    const int b_ = m >> 11;
                    const int s_ = m & 2047;
                    const int h_ = n >> 6;
                    const int d_ = n & 63;
                    *(float2*)&out[(((size_t)(b_ * H_ + h_) * S_ + s_) << 6) + d_] = v;
                } else {
                    *(float2*)&out[(size_t)m * D_ + n] = v;
                }
            }
        }
    }
}

// ---------------------------------------------------------------------------
// Flash attention via mma.sync (causal).
// Block = (q-tile of 128 rows, head, batch). 8 warps, warp = 16 q rows.
// S = Q K^T: 3-term bf16 split; softmax fp32 in C-fragment registers;
// P repacked in-register to A fragments (C cols == A k); P V with 3-term split.
// smem: K [64 seq][64 dh], V^T [64 dh][64 seq], hi+lo, stride 72 bf16.
// ---------------------------------------------------------------------------
constexpr int ARS = 72;  // attn smem row stride in bf16 elements (144 B)

__global__ __launch_bounds__(256)
void attn_mma(const float* __restrict__ Q, const float* __restrict__ K,
              const float* __restrict__ V, float* __restrict__ Out)
{
    __shared__ __nv_bfloat16 Kh[64 * ARS];
    __shared__ __nv_bfloat16 Kl[64 * ARS];
    __shared__ __nv_bfloat16 Vh[64 * ARS];   // transposed: [dh][seq]
    __shared__ __nv_bfloat16 Vl[64 * ARS];

    const int tid  = threadIdx.x;
    const int wid  = tid >> 5;
    const int lane = tid & 31;
    const int lq   = lane >> 2;          // 0..7
    const int c2   = (lane & 3) << 1;    // 0,2,4,6

    const int qt = (int)gridDim.x - 1 - (int)blockIdx.x;   // heavy tiles first
    const int q0 = qt * 128;
    const int h  = blockIdx.y;
    const int b  = blockIdx.z;
    const size_t base = (size_t)(b * H_ + h) * S_ * DH_;
    const int wrow = wid * 16;

    // ---- Load Q fragments (held in registers for the whole block) ----
    uint32_t qh[4][4], ql[4][4];
    {
        const float* q0p = Q + base + (size_t)(q0 + wrow + lq) * DH_;
        const float* q1p = q0p + 8 * DH_;
#pragma unroll
        for (int kt = 0; kt < 4; ++kt) {
            const int col0 = kt * 16 + c2;
            float2 f;
            f = *(const float2*)(q0p + col0);      split2(f.x, f.y, qh[kt][0], ql[kt][0]);
            f = *(const float2*)(q1p + col0);      split2(f.x, f.y, qh[kt][1], ql[kt][1]);
            f = *(const float2*)(q0p + col0 + 8);  split2(f.x, f.y, qh[kt][2], ql[kt][2]);
            f = *(const float2*)(q1p + col0 + 8);  split2(f.x, f.y, qh[kt][3], ql[kt][3]);
        }
    }

    float oacc[8][4];
#pragma unroll
    for (int nt = 0; nt < 8; ++nt)
#pragma unroll
        for (int r = 0; r < 4; ++r) oacc[nt][r] = 0.0f;

    float m0 = -1e30f, m1 = -1e30f, l0 = 0.0f, l1 = 0.0f;

    constexpr float scale = 0.125f;      // 1/sqrt(64)
    const int r0g = q0 + wrow + lq;
    const int r1g = r0g + 8;
    const int rmaxWarp = q0 + wrow + 15;

    for (int k0 = 0; k0 < q0 + 128; k0 += 64) {
        __syncthreads();   // previous tile's fragment reads complete

        // ---- Load K (natural) and V (transposed) tiles, split hi/lo ----
#pragma unroll
        for (int it = 0; it < 4; ++it) {
            const int idx = tid + it * 256;   // 0..1023
            const int r   = idx >> 4;         // seq 0..63
            const int d4  = (idx & 15) << 2;  // dh 0..60
            float4 kf = *(const float4*)(K + base + (size_t)(k0 + r) * DH_ + d4);
            uint32_t h01, l01, h23, l23;
            split2(kf.x, kf.y, h01, l01);
            split2(kf.z, kf.w, h23, l23);
            *(uint32_t*)&Kh[r * ARS + d4]     = h01;
            *(uint32_t*)&Kh[r * ARS + d4 + 2] = h23;
            *(uint32_t*)&Kl[r * ARS + d4]     = l01;
            *(uint32_t*)&Kl[r * ARS + d4 + 2] = l23;

            float4 vf = *(const float4*)(V + base + (size_t)(k0 + r) * DH_ + d4);
            float vv[4] = {vf.x, vf.y, vf.z, vf.w};
#pragma unroll
            for (int j = 0; j < 4; ++j) {
                __nv_bfloat16 hb = __float2bfloat16(vv[j]);
                float res = vv[j] - __bfloat162float(hb);
                Vh[(d4 + j) * ARS + r] = hb;
                Vl[(d4 + j) * ARS + r] = __float2bfloat16(res);
            }
        }
        __syncthreads();

        if (k0 > rmaxWarp) continue;   // warp fully masked for this k tile

        // ---- S = Q K^T (3-term split) ----
        float sc[8][4];
#pragma unroll
        for (int nt = 0; nt < 8; ++nt)
#pragma unroll
            for (int r = 0; r < 4; ++r) sc[nt][r] = 0.0f;

#pragma unroll
        for (int kt = 0; kt < 4; ++kt) {
            const int kb = kt * 16 + c2;
#pragma unroll
            for (int nt = 0; nt < 8; ++nt) {
                const int n = nt * 8 + lq;
                uint32_t bh[2], bl[2];
                bh[0] = *(const uint32_t*)&Kh[n * ARS + kb];
                bh[1] = *(const uint32_t*)&Kh[n * ARS + kb + 8];
                bl[0] = *(const uint32_t*)&Kl[n * ARS + kb];
                bl[1] = *(const uint32_t*)&Kl[n * ARS + kb + 8];
                mma16816(sc[nt], qh[kt], bh);
                mma16816(sc[nt], qh[kt], bl);
                mma16816(sc[nt], ql[kt], bh);
            }
        }

        // ---- scale + causal mask ----
        const bool needMask = (k0 + 64 > q0 + wrow);
#pragma unroll
        for (int nt = 0; nt < 8; ++nt) {
            const int c0g = k0 + nt * 8 + c2;
            sc[nt][0] *= scale; sc[nt][1] *= scale;
            sc[nt][2] *= scale; sc[nt][3] *= scale;
            if (needMask) {
                if (c0g     > r0g) sc[nt][0] = -1e30f;
                if (c0g + 1 > r0g) sc[nt][1] = -1e30f;
                if (c0g     > r1g) sc[nt][2] = -1e30f;
                if (c0g + 1 > r1g) sc[nt][3] = -1e30f;
            }
        }

        // ---- online softmax (quad shuffle reductions) ----
        float mx0 = -1e30f, mx1 = -1e30f;
#pragma unroll
        for (int nt = 0; nt < 8; ++nt) {
            mx0 = fmaxf(mx0, fmaxf(sc[nt][0], sc[nt][1]));
            mx1 = fmaxf(mx1, fmaxf(sc[nt][2], sc[nt][3]));
        }
        mx0 = fmaxf(mx0, __shfl_xor_sync(0xffffffffu, mx0, 1));
        mx0 = fmaxf(mx0, __shfl_xor_sync(0xffffffffu, mx0, 2));
        mx1 = fmaxf(mx1, __shfl_xor_sync(0xffffffffu, mx1, 1));
        mx1 = fmaxf(mx1, __shfl_xor_sync(0xffffffffu, mx1, 2));

        const float mn0 = fmaxf(m0, mx0);
        const float mn1 = fmaxf(m1, mx1);
        const float corr0 = __expf(m0 - mn0);
        const float corr1 = __expf(m1 - mn1);
        m0 = mn0; m1 = mn1;

        float rs0 = 0.0f, rs1 = 0.0f;
#pragma unroll
        for (int nt = 0; nt < 8; ++nt) {
            float p0 = __expf(sc[nt][0] - mn0);
            float p1 = __expf(sc[nt][1] - mn0);
            float p2 = __expf(sc[nt][2] - mn1);
            float p3 = __expf(sc[nt][3] - mn1);
            sc[nt][0] = p0; sc[nt][1] = p1; sc[nt][2] = p2; sc[nt][3] = p3;
            rs0 += p0 + p1;
            rs1 += p2 + p3;
        }
        rs0 += __shfl_xor_sync(0xffffffffu, rs0, 1);
        rs0 += __shfl_xor_sync(0xffffffffu, rs0, 2);
        rs1 += __shfl_xor_sync(0xffffffffu, rs1, 1);
        rs1 += __shfl_xor_sync(0xffffffffu, rs1, 2);
        l0 = l0 * corr0 + rs0;
        l1 = l1 * corr1 + rs1;

#pragma unroll
        for (int nt = 0; nt < 8; ++nt) {
            oacc[nt][0] *= corr0; oacc[nt][1] *= corr0;
            oacc[nt][2] *= corr1; oacc[nt][3] *= corr1;
        }

        // ---- pack P into A fragments (in-register, split hi/lo) ----
        uint32_t ph[4][4], pl[4][4];
#pragma unroll
        for (int kt = 0; kt < 4; ++kt) {
            const int t0 = 2 * kt, t1 = 2 * kt + 1;
            split2(sc[t0][0], sc[t0][1], ph[kt][0], pl[kt][0]);
            split2(sc[t0][2], sc[t0][3], ph[kt][1], pl[kt][1]);
            split2(sc[t1][0], sc[t1][1], ph[kt][2], pl[kt][2]);
            split2(sc[t1][2], sc[t1][3], ph[kt][3], pl[kt][3]);
        }

        // ---- O += P V (3-term split; V^T smem gives B fragments) ----
#pragma unroll
        for (int kt = 0; kt < 4; ++kt) {
            const int kb = kt * 16 + c2;
#pragma unroll
            for (int nt = 0; nt < 8; ++nt) {
                const int n = nt * 8 + lq;       // dh column
                uint32_t vh[2], vl[2];
                vh[0] = *(const uint32_t*)&Vh[n * ARS + kb];
                vh[1] = *(const uint32_t*)&Vh[n * ARS + kb + 8];
                vl[0] = *(const uint32_t*)&Vl[n * ARS + kb];
                vl[1] = *(const uint32_t*)&Vl[n * ARS + kb + 8];
                mma16816(oacc[nt], ph[kt], vh);
                mma16816(oacc[nt], ph[kt], vl);
                mma16816(oacc[nt], pl[kt], vh);
            }
        }
    }

    // ---- epilogue: normalize, write [B,S,D] with head interleave ----
    const float inv0 = 1.0f / l0;
    const float inv1 = 1.0f / l1;
#pragma unroll
    for (int nt = 0; nt < 8; ++nt) {
        const int d = h * DH_ + nt * 8 + c2;
        *(float2*)&Out[(size_t)(b * S_ + r0g) * D_ + d] =
            make_float2(oacc[nt][0] * inv0, oacc[nt][1] * inv0);
        *(float2*)&Out[(size_t)(b * S_ + r1g) * D_ + d] =
            make_float2(oacc[nt][2] * inv1, oacc[nt][3] * inv1);
    }
}

// ---------------------------------------------------------------------------
// Launch
// ---------------------------------------------------------------------------
extern "C" void kernel_launch(void* const* d_in, const int* in_sizes, int n_in,
                              void* d_out, int out_size)
{
    const float* x  = (const float*)d_in[0];
    const float* wq = (const float*)d_in[1];
    const float* wk = (const float*)d_in[2];
    const float* wv = (const float*)d_in[3];
    const float* wo = (const float*)d_in[4];
    float* out = (float*)d_out;

    void *pq, *pk, *pv, *pa;
    cudaGetSymbolAddress(&pq, g_q);
    cudaGetSymbolAddress(&pk, g_k);
    cudaGetSymbolAddress(&pv, g_v);
    cudaGetSymbolAddress(&pa, g_attn);
    float* q  = (float*)pq;
    float* k  = (float*)pk;
    float* v  = (float*)pv;
    float* ao = (float*)pa;

    dim3 gemm_grid(D_ / 128, M_ / 128);   // (8, 32)
    gemm_mma<true><<<gemm_grid, 256>>>(x, wq, q);
    gemm_mma<true><<<gemm_grid, 256>>>(x, wk, k);
    gemm_mma<true><<<gemm_grid, 256>>>(x, wv, v);

    dim3 attn_grid(S_ / 128, H_, B_);     // (16, 16, 2)
    attn_mma<<<attn_grid, 256>>>(q, k, v, ao);

    gemm_mma<false><<<gemm_grid, 256>>>(ao, wo, out);
}